// round 10
// baseline (speedup 1.0000x reference)
#include <cuda_runtime.h>
#include <cuda_bf16.h>
#include <cstdint>

#define G    4096
#define NPG  32
#define NN   (G * NPG)
#define D    256
#define SH   256
#define HDG  50
#define HDN  3

#define OFF_GHEAD 0
#define OFF_NHEAD (G * HDG)
#define OFF_GVAR  (G * HDG + NN * HDN)
#define OFF_NVAR  (2 * G * HDG + NN * HDN)

#define NCTA   2112            // 2 graphs per CTA
#define NSLOT  (NCTA * 2)      // 4224; 128-slot -1 gap separates branches

__device__ float g_xg[G * D];
// W^T bf16 hi/lo, K16-chunk-major: [branch][chunk(16)][split(2)][n(256)][k(16)]
__device__ unsigned short g_Wt[2][16][2][256][16];
__device__ int g_sched[NSLOT];
__device__ int g_cnt[2];

// ---------------- node kernel smem layout (bytes) ----------------
// rows padded to 48B (16B-aligned, ldsm conflict-free: 8 rows hit 8 banks)
#define SMA    0                      // A: 128 rows x 48B = 6144 (hi 0-63, lo 64-127)
#define SMB    6144                   // B: 3 bufs x (512 rows x 48B) = 73728
#define SMW2   79872                  // W2s[256*6] f32 = 6144
#define SMBN   86016                  // bns[256]  f32 = 1024
#define SMRED  87040                  // red[4][64][6] f32 = 6144
#define SMXP   93184                  // xp[8][2][256] f32 = 16384
#define SMGS   109568                 // gsm[2] int (+pad) = 16
#define SMTOT  109584

// ---------------- PTX helpers ----------------
__device__ __forceinline__ uint32_t smem_u32(const void* p) {
    uint32_t a;
    asm("{ .reg .u64 t; cvta.to.shared.u64 t, %1; cvt.u32.u64 %0, t; }" : "=r"(a) : "l"(p));
    return a;
}
__device__ __forceinline__ void ldsm4(uint32_t* r, uint32_t addr) {
    asm volatile("ldmatrix.sync.aligned.m8n8.x4.shared.b16 {%0,%1,%2,%3}, [%4];"
        : "=r"(r[0]), "=r"(r[1]), "=r"(r[2]), "=r"(r[3]) : "r"(addr));
}
__device__ __forceinline__ void ldsm2(uint32_t* r, uint32_t addr) {
    asm volatile("ldmatrix.sync.aligned.m8n8.x2.shared.b16 {%0,%1}, [%2];"
        : "=r"(r[0]), "=r"(r[1]) : "r"(addr));
}
__device__ __forceinline__ void mma_bf16(float* c, const uint32_t* a, const uint32_t* b) {
    asm volatile("mma.sync.aligned.m16n8k16.row.col.f32.bf16.bf16.f32 "
        "{%0,%1,%2,%3}, {%4,%5,%6,%7}, {%8,%9}, {%0,%1,%2,%3};"
        : "+f"(c[0]), "+f"(c[1]), "+f"(c[2]), "+f"(c[3])
        : "r"(a[0]), "r"(a[1]), "r"(a[2]), "r"(a[3]), "r"(b[0]), "r"(b[1]));
}
__device__ __forceinline__ uint32_t pack_bf16(float a, float b) {
    __nv_bfloat162 t = __floats2bfloat162_rn(a, b);
    return *(uint32_t*)&t;
}
#define CP_ASYNC16(dst, src) \
    asm volatile("cp.async.cg.shared.global [%0], [%1], 16;" :: "r"(dst), "l"(src) : "memory")
#define CP_COMMIT()  asm volatile("cp.async.commit_group;" ::: "memory")
#define CP_WAIT0()   asm volatile("cp.async.wait_group 0;" ::: "memory")
#define CP_WAIT1()   asm volatile("cp.async.wait_group 1;" ::: "memory")
#define CP_WAIT2()   asm volatile("cp.async.wait_group 2;" ::: "memory")

// ---------------------------------------------------------------------------
// prep: split Wn1 into bf16 hi/lo W^T images; coalesced kk-contiguous stores
// ---------------------------------------------------------------------------
__global__ void prep_k(const float* __restrict__ Wn1)
{
    int idx = blockIdx.x * blockDim.x + threadIdx.x;  // 131072 total
    int b  = idx >> 16;
    int r  = idx & 65535;
    int c  = r >> 12;          // chunk 0..15
    int n  = (r >> 4) & 255;
    int kk = r & 15;
    int k  = c * 16 + kk;
    float v = Wn1[b * 65536 + k * 256 + n];
    __nv_bfloat16 h = __float2bfloat16(v);
    __nv_bfloat16 l = __float2bfloat16(v - __bfloat162float(h));
    g_Wt[b][c][0][n][kk] = __bfloat16_as_ushort(h);
    g_Wt[b][c][1][n][kk] = __bfloat16_as_ushort(l);
}

// ---------------------------------------------------------------------------
// schedule
// ---------------------------------------------------------------------------
__global__ void sched_init_k()
{
    int i = blockIdx.x * blockDim.x + threadIdx.x;
    if (i < NSLOT) g_sched[i] = -1;
    if (i < 2) g_cnt[i] = 0;
}
__global__ void sched_fill_k(const int* __restrict__ ds)
{
    int g = blockIdx.x * blockDim.x + threadIdx.x;
    if (g >= G) return;
    if (ds[g] == 0) g_sched[atomicAdd(&g_cnt[0], 1)] = g;
    else            g_sched[NSLOT - 1 - atomicAdd(&g_cnt[1], 1)] = g;
}

// ---------------------------------------------------------------------------
// node branch: bf16 HMMA 3-term split. CTA = 2 same-branch graphs = 64 nodes,
// 256 thr (8 warps: 2M x 4N, warp tile 32x64). K=16 chunks, 3-buffer cp.async
// (distance 2). 2 CTAs/SM -> independent barrier domains overlap.
// ---------------------------------------------------------------------------
__global__ void __launch_bounds__(256, 2) node_mma_k(
    const float* __restrict__ x, const int* __restrict__ ds,
    const float* __restrict__ bn1, const float* __restrict__ Wn2,
    const float* __restrict__ bn2, float* __restrict__ out)
{
    extern __shared__ __align__(16) char smem[];
    uint32_t sbase = smem_u32(smem);
    int tid  = threadIdx.x;
    int lane = tid & 31;
    int wid  = tid >> 5;        // 0..7
    int mw   = wid >> 2;        // 0..1 (graph)
    int nw   = wid & 3;         // 0..3

    int* gsm = (int*)(smem + SMGS);
    if (tid < 2) gsm[tid] = g_sched[blockIdx.x * 2 + tid];
    __syncthreads();

    int b = -1, vmask = 0;
#pragma unroll
    for (int r = 0; r < 2; r++) {
        int g = gsm[r];
        if (g >= 0) { vmask |= 1 << r; if (b < 0) b = ds[g]; }
    }
    if (b < 0) return;

    float* W2s = (float*)(smem + SMW2);
    float* bns = (float*)(smem + SMBN);
#pragma unroll
    for (int i = tid; i < 256 * 6; i += 256) W2s[i] = Wn2[b * 1536 + i];
    bns[tid] = bn1[b * 256 + tid];

    float acc[2][8][4];
#pragma unroll
    for (int mt = 0; mt < 2; mt++)
#pragma unroll
        for (int nt = 0; nt < 8; nt++)
#pragma unroll
            for (int q = 0; q < 4; q++) acc[mt][nt][q] = 0.f;

    const float4* x4 = (const float4*)x;
    int arow_t = tid >> 2;          // 0..63 (node row in tile)
    int aq     = tid & 3;           // float4 within chunk
    int ag     = gsm[arow_t >> 5];  // graph of my row
    int agl    = arow_t >> 5;
    size_t axoff = (ag >= 0) ? (size_t)(ag * 32 + (arow_t & 31)) * 64 + aq : 0;

    // ---- prologue: cp.async B chunks 0,1 (two groups); LDG A chunk 0
    const char* wsrc = (const char*)&g_Wt[b][0][0][0][0];   // 16KB per chunk
#pragma unroll
    for (int i = 0; i < 4; i++) {
        int idx = tid + 256 * i;                // 0..1023
        int row = idx >> 1, q = idx & 1;
        CP_ASYNC16(sbase + SMB + (uint32_t)(row * 48 + q * 16), wsrc + idx * 16);
    }
    CP_COMMIT();
#pragma unroll
    for (int i = 0; i < 4; i++) {
        int idx = tid + 256 * i;
        int row = idx >> 1, q = idx & 1;
        CP_ASYNC16(sbase + SMB + 24576 + (uint32_t)(row * 48 + q * 16),
                   wsrc + 16384 + idx * 16);
    }
    CP_COMMIT();
    float4 av = make_float4(0.f, 0.f, 0.f, 0.f);
    if (ag >= 0) av = x4[axoff];

    for (int c = 0; c < 16; c++) {
        uint32_t bbase = SMB + (uint32_t)(c % 3) * 24576;
        // ---- convert + store A chunk c (hi rows 0-63, lo rows 64-127)
        {
            float4 v = av;
            float hx = __bfloat162float(__float2bfloat16(v.x));
            float hy = __bfloat162float(__float2bfloat16(v.y));
            float hz = __bfloat162float(__float2bfloat16(v.z));
            float hw = __bfloat162float(__float2bfloat16(v.w));
            uint2 hi = make_uint2(pack_bf16(v.x, v.y), pack_bf16(v.z, v.w));
            uint2 lo = make_uint2(pack_bf16(v.x - hx, v.y - hy),
                                  pack_bf16(v.z - hz, v.w - hw));
            *(uint2*)(smem + SMA + (uint32_t)(arow_t * 48 + aq * 8))        = hi;
            *(uint2*)(smem + SMA + (uint32_t)((64 + arow_t) * 48 + aq * 8)) = lo;
            // mean partials: rows r, r^1, r^2 summed via lane^4, lane^8
            float vv[4] = {v.x, v.y, v.z, v.w};
#pragma unroll
            for (int t = 0; t < 4; t++) {
                float s = vv[t];
                s += __shfl_xor_sync(0xffffffffu, s, 4);
                s += __shfl_xor_sync(0xffffffffu, s, 8);
                if ((lane & 12) == 0 && ((vmask >> agl) & 1)) {
                    int p = (wid & 3) * 2 + (lane >> 4);   // 0..7
                    ((float*)(smem + SMXP))[(p * 2 + agl) * 256 + c * 16 + aq * 4 + t] = s;
                }
            }
        }
        // ---- prefetch: B chunk c+2, A chunk c+1
        if (c <= 13) {
            const char* src = wsrc + (size_t)(c + 2) * 16384;
            uint32_t nb = SMB + (uint32_t)((c + 2) % 3) * 24576;
#pragma unroll
            for (int i = 0; i < 4; i++) {
                int idx = tid + 256 * i;
                int row = idx >> 1, q = idx & 1;
                CP_ASYNC16(sbase + nb + (uint32_t)(row * 48 + q * 16), src + idx * 16);
            }
            CP_COMMIT();
        }
        if (c < 15 && ag >= 0) av = x4[axoff + (c + 1) * 4];
        if (c < 14) CP_WAIT2();
        else if (c == 14) CP_WAIT1();
        else CP_WAIT0();
        __syncthreads();
        // ---- compute chunk c
        {
            uint32_t Ah[2][4], Al[2][4];
            uint32_t acol2 = (uint32_t)((lane >> 4) << 4);   // byte offset 0/16
#pragma unroll
            for (int mt = 0; mt < 2; mt++) {
                uint32_t arow = (uint32_t)(mw * 32 + mt * 16 + (lane & 15));
                ldsm4(Ah[mt], sbase + SMA + arow * 48 + acol2);
                ldsm4(Al[mt], sbase + SMA + (64 + arow) * 48 + acol2);
            }
            uint32_t bcol2 = (uint32_t)(((lane >> 3) & 1) << 4);
#pragma unroll
            for (int nt = 0; nt < 8; nt++) {
                uint32_t brow = (uint32_t)(nw * 64 + nt * 8 + (lane & 7));
                uint32_t Bh[2], Bl[2];
                ldsm2(Bh, sbase + bbase + brow * 48 + bcol2);
                ldsm2(Bl, sbase + bbase + (256 + brow) * 48 + bcol2);
#pragma unroll
                for (int mt = 0; mt < 2; mt++) {
                    mma_bf16(acc[mt][nt], Ah[mt], Bh);
                    mma_bf16(acc[mt][nt], Ah[mt], Bl);
                    mma_bf16(acc[mt][nt], Al[mt], Bh);
                }
            }
        }
        __syncthreads();   // A/B buffer reuse safety
    }

    // ---- epilogue: bias+ReLU on fragments, partial layer2, reduce
    float pt[4][6];
#pragma unroll
    for (int r = 0; r < 4; r++)
#pragma unroll
        for (int j = 0; j < 6; j++) pt[r][j] = 0.f;

#pragma unroll
    for (int mt = 0; mt < 2; mt++)
#pragma unroll
        for (int nt = 0; nt < 8; nt++) {
            int col = nw * 64 + nt * 8 + (lane & 3) * 2;
            float h00 = fmaxf(acc[mt][nt][0] + bns[col],     0.f);
            float h01 = fmaxf(acc[mt][nt][1] + bns[col + 1], 0.f);
            float h10 = fmaxf(acc[mt][nt][2] + bns[col],     0.f);
            float h11 = fmaxf(acc[mt][nt][3] + bns[col + 1], 0.f);
#pragma unroll
            for (int j = 0; j < 6; j++) {
                float w0 = W2s[col * 6 + j], w1 = W2s[(col + 1) * 6 + j];
                pt[mt * 2][j]     += h00 * w0 + h01 * w1;
                pt[mt * 2 + 1][j] += h10 * w0 + h11 * w1;
            }
        }

    float* red = (float*)(smem + SMRED);
#pragma unroll
    for (int r = 0; r < 4; r++)
#pragma unroll
        for (int j = 0; j < 6; j++) {
            float s = pt[r][j];
            s += __shfl_xor_sync(0xffffffffu, s, 1);
            s += __shfl_xor_sync(0xffffffffu, s, 2);
            if ((lane & 3) == 0) {
                int row = mw * 32 + (r >> 1) * 16 + (lane >> 2) + (r & 1) * 8;
                red[(nw * 64 + row) * 6 + j] = s;
            }
        }
    __syncthreads();

    if (tid < 64) {
        int g = gsm[tid >> 5];
        if (g >= 0) {
            float o[6];
#pragma unroll
            for (int j = 0; j < 6; j++)
                o[j] = bn2[b * 6 + j] + red[tid * 6 + j] + red[(64 + tid) * 6 + j]
                     + red[(128 + tid) * 6 + j] + red[(192 + tid) * 6 + j];
            int node = g * 32 + (tid & 31);
            out[OFF_NHEAD + node * 3 + 0] = o[0];
            out[OFF_NHEAD + node * 3 + 1] = o[1];
            out[OFF_NHEAD + node * 3 + 2] = o[2];
            out[OFF_NVAR  + node * 3 + 0] = o[3] * o[3];
            out[OFF_NVAR  + node * 3 + 1] = o[4] * o[4];
            out[OFF_NVAR  + node * 3 + 2] = o[5] * o[5];
        }
    }

    // ---- write per-graph means (deterministic tree over 8 partials)
    const float* xp = (const float*)(smem + SMXP);
#pragma unroll
    for (int t = tid; t < 512; t += 256) {
        int gl = t >> 8, d = t & 255;
        int g = gsm[gl];
        if (g >= 0) {
            float s = 0.f;
#pragma unroll
            for (int p = 0; p < 8; p++) s += xp[(p * 2 + gl) * 256 + d];
            g_xg[g * 256 + d] = s * (1.0f / NPG);
        }
    }
}

// ---------------------------------------------------------------------------
// graph branch: SIMT fp32, branch-sorted (132 CTAs x 32 graphs, one branch).
// 16-row W tile; 48KB dynamic smem via explicit opt-in attribute.
// ---------------------------------------------------------------------------
__global__ void __launch_bounds__(256) graph_k(
    const int* __restrict__ ds,
    const float* __restrict__ Wgs, const float* __restrict__ bgs,
    const float* __restrict__ Wgh, const float* __restrict__ bgh,
    float* __restrict__ out)
{
    extern __shared__ float smemf[];
    __shared__ int gidx[32];
    float* xs = smemf;                 // 32x256 = 32KB
    float* ws = smemf + 32 * 256;      // 16x256 = 16KB

    int tid = threadIdx.x;
    if (tid < 32) gidx[tid] = g_sched[blockIdx.x * 32 + tid];
    __syncthreads();

    int b = -1;
    for (int r = 0; r < 32; r++) {
        int g = gidx[r];
        if (g >= 0) { b = ds[g]; break; }
    }
    if (b < 0) return;

    for (int j = tid; j < 32 * 64; j += 256) {
        int row = j >> 6, q = j & 63;
        int g = gidx[row];
        if (g >= 0) ((float4*)xs)[j] = ((const float4*)g_xg)[g * 64 + q];
    }

    {
        const float* W = Wgs + (size_t)b * D * SH;
        const float* bias = bgs + b * SH;
        int r0 = (tid >> 5) * 4;
        int c0 = (tid & 31) * 4;
        float acc[4][8];
#pragma unroll
        for (int r = 0; r < 4; r++)
#pragma unroll
            for (int c = 0; c < 8; c++) acc[r][c] = 0.f;

        for (int kt = 0; kt < D; kt += 16) {
            __syncthreads();
            const float4* wsrc = (const float4*)(W + (size_t)kt * SH);
            float4* wdst = (float4*)ws;
#pragma unroll
            for (int j = tid; j < 16 * SH / 4; j += 256) wdst[j] = wsrc[j];
            __syncthreads();
#pragma unroll
            for (int dd = 0; dd < 16; dd++) {
                float xv0 = xs[(r0 + 0) * D + kt + dd];
                float xv1 = xs[(r0 + 1) * D + kt + dd];
                float xv2 = xs[(r0 + 2) * D + kt + dd];
                float xv3 = xs[(r0 + 3) * D + kt + dd];
                float4 wa = *(const float4*)&ws[dd * SH + c0];
                float4 wb = *(const float4*)&ws[dd * SH + c0 + 128];
                float wv[8] = {wa.x, wa.y, wa.z, wa.w, wb.x, wb.y, wb.z, wb.w};
#pragma unroll
                for (int c = 0; c < 8; c++) {
                    acc[0][c] += xv0 * wv[c];
                    acc[1][c] += xv1 * wv[c];
                    acc[2][c] += xv2 * wv[c];
                    acc[3][c] += xv3 * wv[c];
                }
            }
        }
        __syncthreads();
#pragma unroll
        for (int c = 0; c < 4; c++) {
            float b0 = bias[c0 + c];
            float b1 = bias[c0 + 128 + c];
#pragma unroll
            for (int r = 0; r < 4; r++) {
                xs[(r0 + r) * SH + c0 + c]       = fmaxf(acc[r][c]     + b0, 0.f);
                xs[(r0 + r) * SH + c0 + 128 + c] = fmaxf(acc[r][c + 4] + b1, 0.f);
            }
        }
        __syncthreads();
    }

    const float* W2 = Wgh + (size_t)b * SH * (2 * HDG);
    for (int j = tid; j < 32 * 2 * HDG; j += 256) {
        int i = j / (2 * HDG);
        int h = j % (2 * HDG);
        int g = gidx[i];
        if (g < 0) continue;
        float s = bgh[b * 2 * HDG + h];
#pragma unroll 8
        for (int k = 0; k < SH; k++) s += xs[i * SH + k] * W2[k * (2 * HDG) + h];
        if (h < HDG) out[OFF_GHEAD + g * HDG + h] = s;
        else         out[OFF_GVAR  + g * HDG + (h - HDG)] = s * s;
    }
}

// ---------------------------------------------------------------------------
extern "C" void kernel_launch(void* const* d_in, const int* in_sizes, int n_in,
                              void* d_out, int out_size)
{
    const float* x   = (const float*)d_in[0];
    const int*   ds  = (const int*)  d_in[1];
    const float* Wgs = (const float*)d_in[3];
    const float* bgs = (const float*)d_in[4];
    const float* Wgh = (const float*)d_in[5];
    const float* bgh = (const float*)d_in[6];
    const float* Wn1 = (const float*)d_in[7];
    const float* bn1 = (const float*)d_in[8];
    const float* Wn2 = (const float*)d_in[9];
    const float* bn2 = (const float*)d_in[10];
    float* out = (float*)d_out;

    cudaFuncSetAttribute(node_mma_k, cudaFuncAttributeMaxDynamicSharedMemorySize, SMTOT);
    cudaFuncSetAttribute(graph_k,    cudaFuncAttributeMaxDynamicSharedMemorySize, 49152);

    size_t smem_g = (32 * 256 + 16 * 256) * sizeof(float);   // 48KB dynamic

    prep_k<<<512, 256>>>(Wn1);
    sched_init_k<<<17, 256>>>();
    sched_fill_k<<<16, 256>>>(ds);
    node_mma_k<<<NCTA, 256, SMTOT>>>(x, ds, bn1, Wn2, bn2, out);
    graph_k<<<NSLOT / 32, 256, smem_g>>>(ds, Wgs, bgs, Wgh, bgh, out);
}

// round 12
// speedup vs baseline: 1.0487x; 1.0487x over previous
#include <cuda_runtime.h>
#include <cuda_bf16.h>
#include <cstdint>

#define G    4096
#define NPG  32
#define NN   (G * NPG)
#define D    256
#define SH   256
#define HDG  50
#define HDN  3

#define OFF_GHEAD 0
#define OFF_NHEAD (G * HDG)
#define OFF_GVAR  (G * HDG + NN * HDN)
#define OFF_NVAR  (2 * G * HDG + NN * HDN)

#define NCTA   1056
#define NSLOT  (NCTA * 4)      // 4224; 128-slot -1 gap separates branches

__device__ float g_xg[G * D];
// W^T bf16 hi/lo, K32-chunk-major: [branch][chunk(8)][split(2)][n(256)][k(32)]
__device__ unsigned short g_Wt[2][8][2][256][32];
__device__ int g_sched[NSLOT];
__device__ int g_cnt[2];

// ---------------- node kernel smem layout (bytes); rows padded to 80B ------
#define SMA    0                      // A: 2 bufs x (256 rows x 80B) = 40960
#define SMB    40960                  // B: 3 bufs x (512 rows x 80B) = 122880
#define SMW2   163840                 // W2s[256*6] f32 = 6144
#define SMBN   169984                 // bns[256]  f32 = 1024
#define SMRED  171008                 // red[4][128][6] f32 = 12288
#define SMXP   183296                 // xp[8][4][256] f32 = 32768
#define SMGS   216064                 // gsm[4] int = 16
#define SMTOT  216080

// ---------------- PTX helpers ----------------
__device__ __forceinline__ uint32_t smem_u32(const void* p) {
    uint32_t a;
    asm("{ .reg .u64 t; cvta.to.shared.u64 t, %1; cvt.u32.u64 %0, t; }" : "=r"(a) : "l"(p));
    return a;
}
__device__ __forceinline__ void ldsm4(uint32_t* r, uint32_t addr) {
    asm volatile("ldmatrix.sync.aligned.m8n8.x4.shared.b16 {%0,%1,%2,%3}, [%4];"
        : "=r"(r[0]), "=r"(r[1]), "=r"(r[2]), "=r"(r[3]) : "r"(addr));
}
__device__ __forceinline__ void ldsm2(uint32_t* r, uint32_t addr) {
    asm volatile("ldmatrix.sync.aligned.m8n8.x2.shared.b16 {%0,%1}, [%2];"
        : "=r"(r[0]), "=r"(r[1]) : "r"(addr));
}
__device__ __forceinline__ void mma_bf16(float* c, const uint32_t* a, const uint32_t* b) {
    asm volatile("mma.sync.aligned.m16n8k16.row.col.f32.bf16.bf16.f32 "
        "{%0,%1,%2,%3}, {%4,%5,%6,%7}, {%8,%9}, {%0,%1,%2,%3};"
        : "+f"(c[0]), "+f"(c[1]), "+f"(c[2]), "+f"(c[3])
        : "r"(a[0]), "r"(a[1]), "r"(a[2]), "r"(a[3]), "r"(b[0]), "r"(b[1]));
}
__device__ __forceinline__ uint32_t pack_bf16(float a, float b) {
    __nv_bfloat162 t = __floats2bfloat162_rn(a, b);
    return *(uint32_t*)&t;
}
#define CP_ASYNC16(dst, src) \
    asm volatile("cp.async.cg.shared.global [%0], [%1], 16;" :: "r"(dst), "l"(src) : "memory")
#define CP_COMMIT()  asm volatile("cp.async.commit_group;" ::: "memory")
#define CP_WAIT0()   asm volatile("cp.async.wait_group 0;" ::: "memory")
#define CP_WAIT1()   asm volatile("cp.async.wait_group 1;" ::: "memory")

// ---------------------------------------------------------------------------
// prep: split Wn1 into bf16 hi/lo W^T chunk images. 16 CTAs = (branch,chunk);
// smem-staged so both global loads and stores are coalesced.
// ---------------------------------------------------------------------------
__global__ void __launch_bounds__(256) prep_k(const float* __restrict__ Wn1)
{
    __shared__ float ws[32 * 256];
    int b = blockIdx.x >> 3;
    int c = blockIdx.x & 7;
    int tid = threadIdx.x;

    const float4* src = (const float4*)(Wn1 + (size_t)b * 65536 + (size_t)c * 32 * 256);
    float4* wd = (float4*)ws;
#pragma unroll
    for (int i = tid; i < 2048; i += 256) wd[i] = src[i];
    __syncthreads();

    int n = tid;
    uint32_t hibuf[16], lobuf[16];
#pragma unroll
    for (int j = 0; j < 16; j++) {
        float v0 = ws[(2 * j)     * 256 + n];
        float v1 = ws[(2 * j + 1) * 256 + n];
        float h0 = __bfloat162float(__float2bfloat16(v0));
        float h1 = __bfloat162float(__float2bfloat16(v1));
        hibuf[j] = pack_bf16(v0, v1);
        lobuf[j] = pack_bf16(v0 - h0, v1 - h1);
    }
    uint4* dhi = (uint4*)&g_Wt[b][c][0][n][0];
    uint4* dlo = (uint4*)&g_Wt[b][c][1][n][0];
#pragma unroll
    for (int q = 0; q < 4; q++) {
        dhi[q] = ((uint4*)hibuf)[q];
        dlo[q] = ((uint4*)lobuf)[q];
    }
}

// ---------------------------------------------------------------------------
// schedule: bucket graphs by branch (branch0 ascending, branch1 descending)
// ---------------------------------------------------------------------------
__global__ void sched_init_k()
{
    int i = blockIdx.x * blockDim.x + threadIdx.x;
    if (i < NSLOT) g_sched[i] = -1;
    if (i < 2) g_cnt[i] = 0;
}
__global__ void sched_fill_k(const int* __restrict__ ds)
{
    int g = blockIdx.x * blockDim.x + threadIdx.x;
    if (g >= G) return;
    if (ds[g] == 0) g_sched[atomicAdd(&g_cnt[0], 1)] = g;
    else            g_sched[NSLOT - 1 - atomicAdd(&g_cnt[1], 1)] = g;
}

// ---------------------------------------------------------------------------
// node branch: bf16 HMMA 3-term split. CTA = 4 same-branch graphs = 128 nodes,
// 512 thr (4M x 4N warps, warp tile 32x64). K=32 chunks; A double-buffered,
// B triple-buffered cp.async; ONE __syncthreads per chunk.
// ---------------------------------------------------------------------------
__global__ void __launch_bounds__(512, 1) node_mma_k(
    const float* __restrict__ x, const int* __restrict__ ds,
    const float* __restrict__ bn1, const float* __restrict__ Wn2,
    const float* __restrict__ bn2, float* __restrict__ out)
{
    extern __shared__ __align__(16) char smem[];
    uint32_t sbase = smem_u32(smem);
    int tid  = threadIdx.x;
    int lane = tid & 31;
    int wid  = tid >> 5;
    int mw   = wid >> 2;
    int nw   = wid & 3;

    int* gsm = (int*)(smem + SMGS);
    if (tid < 4) gsm[tid] = g_sched[blockIdx.x * 4 + tid];
    __syncthreads();

    int b = -1, vmask = 0;
#pragma unroll
    for (int r = 0; r < 4; r++) {
        int g = gsm[r];
        if (g >= 0) { vmask |= 1 << r; if (b < 0) b = ds[g]; }
    }
    if (b < 0) return;

    float* W2s = (float*)(smem + SMW2);
    float* bns = (float*)(smem + SMBN);
    for (int i = tid; i < 256 * 6; i += 512) W2s[i] = Wn2[b * 1536 + i];
    if (tid < 256) bns[tid] = bn1[b * 256 + tid];

    float acc[2][8][4];
#pragma unroll
    for (int mt = 0; mt < 2; mt++)
#pragma unroll
        for (int nt = 0; nt < 8; nt++)
#pragma unroll
            for (int q = 0; q < 4; q++) acc[mt][nt][q] = 0.f;

    // per-thread A row mapping (constant across chunks)
    const float4* x4 = (const float4*)x;
    int row0 = tid >> 3;            // i=0 row (0..63); i=1 row = row0+64
    int aq   = tid & 7;             // float4 within 32-float chunk row
    int g0r  = gsm[row0 >> 5];
    int g1r  = gsm[(row0 + 64) >> 5];
    size_t axof0 = (g0r >= 0) ? (size_t)(g0r * 32 + (row0 & 31)) * 64 + aq : 0;
    size_t axof1 = (g1r >= 0) ? (size_t)(g1r * 32 + ((row0 + 64) & 31)) * 64 + aq : 0;

    const char* wsrc = (const char*)&g_Wt[b][0][0][0][0];   // 32KB per chunk

    // ---- B cp.async for one chunk (2048 uint4; 4 per thread) ----
#define ISSUE_B(cc) do {                                                        \
        const char* _s = wsrc + (size_t)(cc) * 32768;                           \
        uint32_t _d = sbase + SMB + (uint32_t)((cc) % 3) * 40960;               \
        _Pragma("unroll")                                                       \
        for (int _i = 0; _i < 4; _i++) {                                        \
            int _idx = tid + 512 * _i;                                          \
            int _row = _idx >> 2, _q = _idx & 3;                                \
            CP_ASYNC16(_d + (uint32_t)(_row * 80 + _q * 16), _s + _idx * 16);   \
        }                                                                       \
        CP_COMMIT();                                                            \
    } while (0)

    // ---- convert av -> A smem buf + mean partials for chunk cc ----
#define STORE_A(cc, AV0, AV1) do {                                              \
        uint32_t _ab = SMA + (uint32_t)((cc) & 1) * 20480;                      \
        float4 _vv[2] = {AV0, AV1};                                             \
        _Pragma("unroll")                                                       \
        for (int _i = 0; _i < 2; _i++) {                                        \
            int _row = row0 + 64 * _i;                                          \
            float4 _v = _vv[_i];                                                \
            float _hx = __bfloat162float(__float2bfloat16(_v.x));               \
            float _hy = __bfloat162float(__float2bfloat16(_v.y));               \
            float _hz = __bfloat162float(__float2bfloat16(_v.z));               \
            float _hw = __bfloat162float(__float2bfloat16(_v.w));               \
            uint2 _hi = make_uint2(pack_bf16(_v.x, _v.y), pack_bf16(_v.z, _v.w)); \
            uint2 _lo = make_uint2(pack_bf16(_v.x - _hx, _v.y - _hy),           \
                                   pack_bf16(_v.z - _hz, _v.w - _hw));          \
            *(uint2*)(smem + _ab + (uint32_t)(_row * 80 + aq * 8))         = _hi; \
            *(uint2*)(smem + _ab + (uint32_t)((128 + _row) * 80 + aq * 8)) = _lo; \
            float _f[4] = {_v.x, _v.y, _v.z, _v.w};                             \
            _Pragma("unroll")                                                   \
            for (int _t = 0; _t < 4; _t++) {                                    \
                float _s2 = _f[_t];                                             \
                _s2 += __shfl_xor_sync(0xffffffffu, _s2, 8);                    \
                _s2 += __shfl_xor_sync(0xffffffffu, _s2, 16);                   \
                if ((lane & 24) == 0) {                                         \
                    int _gl = _row >> 5;                                        \
                    if ((vmask >> _gl) & 1) {                                   \
                        int _p = (_row >> 2) & 7;                               \
                        ((float*)(smem + SMXP))[(_p * 4 + _gl) * 256 + (cc) * 32 + aq * 4 + _t] = _s2; \
                    }                                                           \
                }                                                               \
            }                                                                   \
        }                                                                       \
    } while (0)

    // ---- prologue ----
    ISSUE_B(0);
    ISSUE_B(1);
    float4 av0 = make_float4(0.f, 0.f, 0.f, 0.f), av1 = av0;
    if (g0r >= 0) av0 = x4[axof0];
    if (g1r >= 0) av1 = x4[axof1];
    STORE_A(0, av0, av1);                    // chunk 0 -> abuf 0
    if (g0r >= 0) av0 = x4[axof0 + 8];       // chunk 1 data
    if (g1r >= 0) av1 = x4[axof1 + 8];

    for (int c = 0; c < 8; c++) {
        if (c < 7) CP_WAIT1(); else CP_WAIT0();
        __syncthreads();   // B(c) visible; A(c) stores visible; bufs to write freed
        // ---- compute chunk c ----
        {
            uint32_t abase = SMA + (uint32_t)(c & 1) * 20480;
            uint32_t bbase = SMB + (uint32_t)(c % 3) * 40960;
#pragma unroll
            for (int ks = 0; ks < 2; ks++) {
                uint32_t Ah[2][4], Al[2][4];
                uint32_t acb = (uint32_t)(ks * 32 + ((lane >> 4) << 4));
#pragma unroll
                for (int mt = 0; mt < 2; mt++) {
                    uint32_t arow = (uint32_t)(mw * 32 + mt * 16 + (lane & 15));
                    ldsm4(Ah[mt], sbase + abase + arow * 80 + acb);
                    ldsm4(Al[mt], sbase + abase + (128 + arow) * 80 + acb);
                }
                uint32_t bcb = (uint32_t)(ks * 32 + (((lane >> 3) & 1) << 4));
#pragma unroll
                for (int nt = 0; nt < 8; nt++) {
                    uint32_t brow = (uint32_t)(nw * 64 + nt * 8 + (lane & 7));
                    uint32_t Bh[2], Bl[2];
                    ldsm2(Bh, sbase + bbase + brow * 80 + bcb);
                    ldsm2(Bl, sbase + bbase + (256 + brow) * 80 + bcb);
#pragma unroll
                    for (int mt = 0; mt < 2; mt++) {
                        mma_bf16(acc[mt][nt], Ah[mt], Bh);
                        mma_bf16(acc[mt][nt], Ah[mt], Bl);
                        mma_bf16(acc[mt][nt], Al[mt], Bh);
                    }
                }
            }
        }
        // ---- stage next data (no extra barrier) ----
        if (c < 7) {
            STORE_A(c + 1, av0, av1);        // into abuf[(c+1)&1], read next iter
            if (c < 6) {
                if (g0r >= 0) av0 = x4[axof0 + (c + 2) * 8];
                if (g1r >= 0) av1 = x4[axof1 + (c + 2) * 8];
                ISSUE_B(c + 2);              // into bbuf[(c+2)%3], freed last iter
            }
        }
    }

    // ---- epilogue: bias+ReLU on fragments, partial layer2, reduce ----
    float pt[4][6];
#pragma unroll
    for (int r = 0; r < 4; r++)
#pragma unroll
        for (int j = 0; j < 6; j++) pt[r][j] = 0.f;

#pragma unroll
    for (int mt = 0; mt < 2; mt++)
#pragma unroll
        for (int nt = 0; nt < 8; nt++) {
            int col = nw * 64 + nt * 8 + (lane & 3) * 2;
            float h00 = fmaxf(acc[mt][nt][0] + bns[col],     0.f);
            float h01 = fmaxf(acc[mt][nt][1] + bns[col + 1], 0.f);
            float h10 = fmaxf(acc[mt][nt][2] + bns[col],     0.f);
            float h11 = fmaxf(acc[mt][nt][3] + bns[col + 1], 0.f);
#pragma unroll
            for (int j = 0; j < 6; j++) {
                float w0 = W2s[col * 6 + j], w1 = W2s[(col + 1) * 6 + j];
                pt[mt * 2][j]     += h00 * w0 + h01 * w1;
                pt[mt * 2 + 1][j] += h10 * w0 + h11 * w1;
            }
        }

    float* red = (float*)(smem + SMRED);
#pragma unroll
    for (int r = 0; r < 4; r++)
#pragma unroll
        for (int j = 0; j < 6; j++) {
            float s = pt[r][j];
            s += __shfl_xor_sync(0xffffffffu, s, 1);
            s += __shfl_xor_sync(0xffffffffu, s, 2);
            if ((lane & 3) == 0) {
                int row = mw * 32 + (r >> 1) * 16 + (lane >> 2) + (r & 1) * 8;
                red[(nw * 128 + row) * 6 + j] = s;
            }
        }
    __syncthreads();

    if (tid < 128) {
        int g = gsm[tid >> 5];
        if (g >= 0) {
            float o[6];
#pragma unroll
            for (int j = 0; j < 6; j++)
                o[j] = bn2[b * 6 + j] + red[tid * 6 + j] + red[(128 + tid) * 6 + j]
                     + red[(256 + tid) * 6 + j] + red[(384 + tid) * 6 + j];
            int node = g * 32 + (tid & 31);
            out[OFF_NHEAD + node * 3 + 0] = o[0];
            out[OFF_NHEAD + node * 3 + 1] = o[1];
            out[OFF_NHEAD + node * 3 + 2] = o[2];
            out[OFF_NVAR  + node * 3 + 0] = o[3] * o[3];
            out[OFF_NVAR  + node * 3 + 1] = o[4] * o[4];
            out[OFF_NVAR  + node * 3 + 2] = o[5] * o[5];
        }
    }

    // ---- write per-graph means (deterministic tree over 8 partials) ----
    const float* xp = (const float*)(smem + SMXP);
#pragma unroll
    for (int t = tid; t < 1024; t += 512) {
        int gl = t >> 8, d = t & 255;
        int g = gsm[gl];
        if (g >= 0) {
            float s = 0.f;
#pragma unroll
            for (int p = 0; p < 8; p++) s += xp[(p * 4 + gl) * 256 + d];
            g_xg[g * 256 + d] = s * (1.0f / NPG);
        }
    }
}

// ---------------------------------------------------------------------------
// graph branch: SIMT fp32, branch-sorted (132 CTAs x 32 graphs, one branch).
// ---------------------------------------------------------------------------
__global__ void __launch_bounds__(256) graph_k(
    const int* __restrict__ ds,
    const float* __restrict__ Wgs, const float* __restrict__ bgs,
    const float* __restrict__ Wgh, const float* __restrict__ bgh,
    float* __restrict__ out)
{
    extern __shared__ float smemf[];
    __shared__ int gidx[32];
    float* xs = smemf;                 // 32x256 = 32KB
    float* ws = smemf + 32 * 256;      // 16x256 = 16KB

    int tid = threadIdx.x;
    if (tid < 32) gidx[tid] = g_sched[blockIdx.x * 32 + tid];
    __syncthreads();

    int b = -1;
    for (int r = 0; r < 32; r++) {
        int g = gidx[r];
        if (g >= 0) { b = ds[g]; break; }
    }
    if (b < 0) return;

    for (int j = tid; j < 32 * 64; j += 256) {
        int row = j >> 6, q = j & 63;
        int g = gidx[row];
        if (g >= 0) ((float4*)xs)[j] = ((const float4*)g_xg)[g * 64 + q];
    }

    {
        const float* W = Wgs + (size_t)b * D * SH;
        const float* bias = bgs + b * SH;
        int r0 = (tid >> 5) * 4;
        int c0 = (tid & 31) * 4;
        float acc[4][8];
#pragma unroll
        for (int r = 0; r < 4; r++)
#pragma unroll
            for (int c = 0; c < 8; c++) acc[r][c] = 0.f;

        for (int kt = 0; kt < D; kt += 16) {
            __syncthreads();
            const float4* wsrc = (const float4*)(W + (size_t)kt * SH);
            float4* wdst = (float4*)ws;
#pragma unroll
            for (int j = tid; j < 16 * SH / 4; j += 256) wdst[j] = wsrc[j];
            __syncthreads();
#pragma unroll
            for (int dd = 0; dd < 16; dd++) {
                float xv0 = xs[(r0 + 0) * D + kt + dd];
                float xv1 = xs[(r0 + 1) * D + kt + dd];
                float xv2 = xs[(r0 + 2) * D + kt + dd];
                float xv3 = xs[(r0 + 3) * D + kt + dd];
                float4 wa = *(const float4*)&ws[dd * SH + c0];
                float4 wb = *(const float4*)&ws[dd * SH + c0 + 128];
                float wv[8] = {wa.x, wa.y, wa.z, wa.w, wb.x, wb.y, wb.z, wb.w};
#pragma unroll
                for (int c = 0; c < 8; c++) {
                    acc[0][c] += xv0 * wv[c];
                    acc[1][c] += xv1 * wv[c];
                    acc[2][c] += xv2 * wv[c];
                    acc[3][c] += xv3 * wv[c];
                }
            }
        }
        __syncthreads();
#pragma unroll
        for (int c = 0; c < 4; c++) {
            float b0 = bias[c0 + c];
            float b1 = bias[c0 + 128 + c];
#pragma unroll
            for (int r = 0; r < 4; r++) {
                xs[(r0 + r) * SH + c0 + c]       = fmaxf(acc[r][c]     + b0, 0.f);
                xs[(r0 + r) * SH + c0 + 128 + c] = fmaxf(acc[r][c + 4] + b1, 0.f);
            }
        }
        __syncthreads();
    }

    const float* W2 = Wgh + (size_t)b * SH * (2 * HDG);
    for (int j = tid; j < 32 * 2 * HDG; j += 256) {
        int i = j / (2 * HDG);
        int h = j % (2 * HDG);
        int g = gidx[i];
        if (g < 0) continue;
        float s = bgh[b * 2 * HDG + h];
#pragma unroll 8
        for (int k = 0; k < SH; k++) s += xs[i * SH + k] * W2[k * (2 * HDG) + h];
        if (h < HDG) out[OFF_GHEAD + g * HDG + h] = s;
        else         out[OFF_GVAR  + g * HDG + (h - HDG)] = s * s;
    }
}

// ---------------------------------------------------------------------------
extern "C" void kernel_launch(void* const* d_in, const int* in_sizes, int n_in,
                              void* d_out, int out_size)
{
    const float* x   = (const float*)d_in[0];
    const int*   ds  = (const int*)  d_in[1];
    const float* Wgs = (const float*)d_in[3];
    const float* bgs = (const float*)d_in[4];
    const float* Wgh = (const float*)d_in[5];
    const float* bgh = (const float*)d_in[6];
    const float* Wn1 = (const float*)d_in[7];
    const float* bn1 = (const float*)d_in[8];
    const float* Wn2 = (const float*)d_in[9];
    const float* bn2 = (const float*)d_in[10];
    float* out = (float*)d_out;

    cudaFuncSetAttribute(node_mma_k, cudaFuncAttributeMaxDynamicSharedMemorySize, SMTOT);
    cudaFuncSetAttribute(graph_k,    cudaFuncAttributeMaxDynamicSharedMemorySize, 49152);

    size_t smem_g = (32 * 256 + 16 * 256) * sizeof(float);   // 48KB dynamic

    prep_k<<<16, 256>>>(Wn1);
    sched_init_k<<<17, 256>>>();
    sched_fill_k<<<16, 256>>>(ds);
    node_mma_k<<<NCTA, 512, SMTOT>>>(x, ds, bn1, Wn2, bn2, out);
    graph_k<<<NSLOT / 32, 256, smem_g>>>(ds, Wgs, bgs, Wgh, bgh, out);
}

// round 13
// speedup vs baseline: 1.0831x; 1.0328x over previous
#include <cuda_runtime.h>
#include <cuda_bf16.h>
#include <cstdint>

#define G    4096
#define NPG  32
#define NN   (G * NPG)
#define D    256
#define SH   256
#define HDG  50
#define HDN  3

#define OFF_GHEAD 0
#define OFF_NHEAD (G * HDG)
#define OFF_GVAR  (G * HDG + NN * HDN)
#define OFF_NVAR  (2 * G * HDG + NN * HDN)

#define NCTA   1056
#define NSLOT  (NCTA * 4)      // 4224; 128-slot -1 gap separates branches

__device__ float g_xg[G * D];
// W^T bf16 hi/lo, K32-chunk-major: [branch][chunk(8)][split(2)][n(256)][k(32)]
__device__ unsigned short g_Wt[2][8][2][256][32];
__device__ int g_sched[NSLOT];
__device__ int g_cnt[2];

// ---------------- node kernel smem layout (bytes) ----------------
// A image: full K=256, rows 0-127 hi, 128-255 lo; stride 528B (conflict-free)
#define SMA    0                       // 256 * 528 = 135168
#define SMB    135168                  // B: 2 bufs x (512 rows x 80B) = 81920
#define SMXP   (SMB + 40960)           // mean partials [8][256] float4 = 16384 (buf1, prologue only)
#define SMW2   SMB                     // epilogue: W2s[256*6] f32 (buf area reused)
#define SMBN   (SMB + 6144)            // epilogue: bns[256] f32
#define SMRED  (SMB + 7168)            // epilogue: red[4][128][6] f32 = 12288
#define SMTOT  217088

// ---------------- PTX helpers ----------------
__device__ __forceinline__ uint32_t smem_u32(const void* p) {
    uint32_t a;
    asm("{ .reg .u64 t; cvta.to.shared.u64 t, %1; cvt.u32.u64 %0, t; }" : "=r"(a) : "l"(p));
    return a;
}
__device__ __forceinline__ void ldsm4(uint32_t* r, uint32_t addr) {
    asm volatile("ldmatrix.sync.aligned.m8n8.x4.shared.b16 {%0,%1,%2,%3}, [%4];"
        : "=r"(r[0]), "=r"(r[1]), "=r"(r[2]), "=r"(r[3]) : "r"(addr));
}
__device__ __forceinline__ void mma_bf16(float* c, const uint32_t* a, const uint32_t* b) {
    asm volatile("mma.sync.aligned.m16n8k16.row.col.f32.bf16.bf16.f32 "
        "{%0,%1,%2,%3}, {%4,%5,%6,%7}, {%8,%9}, {%0,%1,%2,%3};"
        : "+f"(c[0]), "+f"(c[1]), "+f"(c[2]), "+f"(c[3])
        : "r"(a[0]), "r"(a[1]), "r"(a[2]), "r"(a[3]), "r"(b[0]), "r"(b[1]));
}
__device__ __forceinline__ uint32_t pack_bf16(float a, float b) {
    __nv_bfloat162 t = __floats2bfloat162_rn(a, b);
    return *(uint32_t*)&t;
}
#define CP_ASYNC16(dst, src) \
    asm volatile("cp.async.cg.shared.global [%0], [%1], 16;" :: "r"(dst), "l"(src) : "memory")
#define CP_COMMIT()  asm volatile("cp.async.commit_group;" ::: "memory")
#define CP_WAIT0()   asm volatile("cp.async.wait_group 0;" ::: "memory")
#define CP_WAIT1()   asm volatile("cp.async.wait_group 1;" ::: "memory")

// ---------------------------------------------------------------------------
// prep: split Wn1 into bf16 hi/lo W^T chunk images (coalesced both ways)
// ---------------------------------------------------------------------------
__global__ void __launch_bounds__(256) prep_k(const float* __restrict__ Wn1)
{
    __shared__ float ws[32 * 256];
    int b = blockIdx.x >> 3;
    int c = blockIdx.x & 7;
    int tid = threadIdx.x;

    const float4* src = (const float4*)(Wn1 + (size_t)b * 65536 + (size_t)c * 32 * 256);
    float4* wd = (float4*)ws;
#pragma unroll
    for (int i = tid; i < 2048; i += 256) wd[i] = src[i];
    __syncthreads();

    int n = tid;
    uint32_t hibuf[16], lobuf[16];
#pragma unroll
    for (int j = 0; j < 16; j++) {
        float v0 = ws[(2 * j)     * 256 + n];
        float v1 = ws[(2 * j + 1) * 256 + n];
        float h0 = __bfloat162float(__float2bfloat16(v0));
        float h1 = __bfloat162float(__float2bfloat16(v1));
        hibuf[j] = pack_bf16(v0, v1);
        lobuf[j] = pack_bf16(v0 - h0, v1 - h1);
    }
    uint4* dhi = (uint4*)&g_Wt[b][c][0][n][0];
    uint4* dlo = (uint4*)&g_Wt[b][c][1][n][0];
#pragma unroll
    for (int q = 0; q < 4; q++) {
        dhi[q] = ((uint4*)hibuf)[q];
        dlo[q] = ((uint4*)lobuf)[q];
    }
}

// ---------------------------------------------------------------------------
// schedule: bucket graphs by branch (branch0 ascending, branch1 descending)
// ---------------------------------------------------------------------------
__global__ void sched_init_k()
{
    int i = blockIdx.x * blockDim.x + threadIdx.x;
    if (i < NSLOT) g_sched[i] = -1;
    if (i < 2) g_cnt[i] = 0;
}
__global__ void sched_fill_k(const int* __restrict__ ds)
{
    int g = blockIdx.x * blockDim.x + threadIdx.x;
    if (g >= G) return;
    if (ds[g] == 0) g_sched[atomicAdd(&g_cnt[0], 1)] = g;
    else            g_sched[NSLOT - 1 - atomicAdd(&g_cnt[1], 1)] = g;
}

// ---------------------------------------------------------------------------
// node branch: bf16 HMMA 3-term split. CTA = 4 same-branch graphs = 128 nodes,
// 512 thr (4M x 4N warps, 32x64 warp tile). A converted ONCE to full-K smem
// image (mean fused); mainloop = pure ldsm+mma with double-buffered cp.async B.
// ---------------------------------------------------------------------------
__global__ void __launch_bounds__(512, 1) node_mma_k(
    const float* __restrict__ x, const int* __restrict__ ds,
    const float* __restrict__ bn1, const float* __restrict__ Wn2,
    const float* __restrict__ bn2, float* __restrict__ out)
{
    extern __shared__ __align__(16) char smem[];
    __shared__ int gsm[4];
    uint32_t sbase = smem_u32(smem);
    int tid  = threadIdx.x;
    int lane = tid & 31;
    int wid  = tid >> 5;
    int mw   = wid >> 2;
    int nw   = wid & 3;

    if (tid < 4) gsm[tid] = g_sched[blockIdx.x * 4 + tid];
    __syncthreads();

    int b = -1;
#pragma unroll
    for (int r = 0; r < 4; r++) {
        int g = gsm[r];
        if (g >= 0 && b < 0) b = ds[g];
    }
    if (b < 0) return;

    const char* wsrc = (const char*)&g_Wt[b][0][0][0][0];   // 32KB per chunk

#define ISSUE_B(cc) do {                                                        \
        const char* _s = wsrc + (size_t)(cc) * 32768;                           \
        uint32_t _d = sbase + SMB + (uint32_t)((cc) & 1) * 40960;               \
        _Pragma("unroll")                                                       \
        for (int _i = 0; _i < 4; _i++) {                                        \
            int _idx = tid + 512 * _i;                                          \
            int _row = _idx >> 2, _q = _idx & 3;                                \
            CP_ASYNC16(_d + (uint32_t)(_row * 80 + _q * 16), _s + _idx * 16);   \
        }                                                                       \
        CP_COMMIT();                                                            \
    } while (0)

    ISSUE_B(0);   // buf0 busy from here; xp lives in buf1 until B1 issued

    // ---- convert x -> A image (hi rows 0-127, lo 128-255) + mean partials ----
    {
        const float4* x4 = (const float4*)x;
        int aq = tid & 63;          // float4 column (d = aq*4..aq*4+3)
        int j  = tid >> 6;          // 0..7
        float4 ms[4];
#pragma unroll
        for (int g = 0; g < 4; g++) ms[g] = make_float4(0.f, 0.f, 0.f, 0.f);

#pragma unroll
        for (int p = 0; p < 2; p++) {
            float4 v[8];
#pragma unroll
            for (int i = 0; i < 8; i++) {
                int ii = p * 8 + i;
                int row = j + 8 * ii;            // 0..127
                int g = gsm[ii >> 2];
                v[i] = (g >= 0) ? x4[(size_t)(g * 32 + (row & 31)) * 64 + aq]
                                : make_float4(0.f, 0.f, 0.f, 0.f);
            }
#pragma unroll
            for (int i = 0; i < 8; i++) {
                int ii = p * 8 + i;
                int row = j + 8 * ii;
                int gl = ii >> 2;
                float4 vv = v[i];
                ms[gl].x += vv.x; ms[gl].y += vv.y;
                ms[gl].z += vv.z; ms[gl].w += vv.w;
                float hx = __bfloat162float(__float2bfloat16(vv.x));
                float hy = __bfloat162float(__float2bfloat16(vv.y));
                float hz = __bfloat162float(__float2bfloat16(vv.z));
                float hw = __bfloat162float(__float2bfloat16(vv.w));
                uint2 hi = make_uint2(pack_bf16(vv.x, vv.y), pack_bf16(vv.z, vv.w));
                uint2 lo = make_uint2(pack_bf16(vv.x - hx, vv.y - hy),
                                      pack_bf16(vv.z - hz, vv.w - hw));
                *(uint2*)(smem + SMA + (uint32_t)(row * 528 + aq * 8))         = hi;
                *(uint2*)(smem + SMA + (uint32_t)((128 + row) * 528 + aq * 8)) = lo;
            }
        }
        // partials: xp[j][g*64+aq] (float4)
        float4* xp = (float4*)(smem + SMXP);
#pragma unroll
        for (int g = 0; g < 4; g++) xp[j * 256 + g * 64 + aq] = ms[g];
    }
    __syncthreads();

    // ---- finalize per-graph means -> g_xg (256 float4 items, tid<256) ----
    if (tid < 256) {
        const float4* xp = (const float4*)(smem + SMXP);
        float4 s = make_float4(0.f, 0.f, 0.f, 0.f);
#pragma unroll
        for (int jj = 0; jj < 8; jj++) {
            float4 t = xp[jj * 256 + tid];
            s.x += t.x; s.y += t.y; s.z += t.z; s.w += t.w;
        }
        int g = gsm[tid >> 6];
        if (g >= 0) {
            s.x *= (1.f / NPG); s.y *= (1.f / NPG);
            s.z *= (1.f / NPG); s.w *= (1.f / NPG);
            ((float4*)g_xg)[g * 64 + (tid & 63)] = s;
        }
    }
    __syncthreads();          // xp consumed; buf1 now free
    ISSUE_B(1);

    float acc[2][8][4];
#pragma unroll
    for (int mt = 0; mt < 2; mt++)
#pragma unroll
        for (int nt = 0; nt < 8; nt++)
#pragma unroll
            for (int q = 0; q < 4; q++) acc[mt][nt][q] = 0.f;

    // ---- mainloop: pure ldsm + mma ----
    for (int c = 0; c < 8; c++) {
        if (c < 7) CP_WAIT1(); else CP_WAIT0();
        __syncthreads();
        uint32_t bbase = SMB + (uint32_t)(c & 1) * 40960;
        uint32_t acol0 = (uint32_t)(c * 64 + ((lane >> 4) << 4));
        uint32_t bcb0  = (uint32_t)(((lane >> 3) & 1) << 4);
        uint32_t brow0 = (uint32_t)(nw * 64 + (lane & 7) + ((lane >> 4) & 1) * 8);
#pragma unroll
        for (int ks = 0; ks < 2; ks++) {
            uint32_t Ah[2][4], Al[2][4];
            uint32_t acb = acol0 + (uint32_t)(ks * 32);
#pragma unroll
            for (int mt = 0; mt < 2; mt++) {
                uint32_t arow = (uint32_t)(mw * 32 + mt * 16 + (lane & 15));
                ldsm4(Ah[mt], sbase + SMA + arow * 528 + acb);
                ldsm4(Al[mt], sbase + SMA + (128 + arow) * 528 + acb);
            }
            uint32_t bcb = bcb0 + (uint32_t)(ks * 32);
#pragma unroll
            for (int p = 0; p < 4; p++) {
                uint32_t Bh[4], Bl[4];
                uint32_t r = brow0 + (uint32_t)(p * 16);
                ldsm4(Bh, sbase + bbase + r * 80 + bcb);
                ldsm4(Bl, sbase + bbase + (256 + r) * 80 + bcb);
#pragma unroll
                for (int sub = 0; sub < 2; sub++) {
#pragma unroll
                    for (int mt = 0; mt < 2; mt++) {
                        mma_bf16(acc[mt][2 * p + sub], Ah[mt], &Bh[2 * sub]);
                        mma_bf16(acc[mt][2 * p + sub], Ah[mt], &Bl[2 * sub]);
                        mma_bf16(acc[mt][2 * p + sub], Al[mt], &Bh[2 * sub]);
                    }
                }
            }
        }
        __syncthreads();
        if (c < 6) ISSUE_B(c + 2);
    }

    // ---- epilogue: load W2/bias into freed B region, fuse bias+ReLU+layer2 ----
    float* W2s = (float*)(smem + SMW2);
    float* bns = (float*)(smem + SMBN);
    for (int i = tid; i < 256 * 6; i += 512) W2s[i] = Wn2[b * 1536 + i];
    if (tid < 256) bns[tid] = bn1[b * 256 + tid];
    __syncthreads();

    float pt[4][6];
#pragma unroll
    for (int r = 0; r < 4; r++)
#pragma unroll
        for (int j = 0; j < 6; j++) pt[r][j] = 0.f;

#pragma unroll
    for (int mt = 0; mt < 2; mt++)
#pragma unroll
        for (int nt = 0; nt < 8; nt++) {
            int col = nw * 64 + nt * 8 + (lane & 3) * 2;
            float h00 = fmaxf(acc[mt][nt][0] + bns[col],     0.f);
            float h01 = fmaxf(acc[mt][nt][1] + bns[col + 1], 0.f);
            float h10 = fmaxf(acc[mt][nt][2] + bns[col],     0.f);
            float h11 = fmaxf(acc[mt][nt][3] + bns[col + 1], 0.f);
#pragma unroll
            for (int j = 0; j < 6; j++) {
                float w0 = W2s[col * 6 + j], w1 = W2s[(col + 1) * 6 + j];
                pt[mt * 2][j]     += h00 * w0 + h01 * w1;
                pt[mt * 2 + 1][j] += h10 * w0 + h11 * w1;
            }
        }

    float* red = (float*)(smem + SMRED);
#pragma unroll
    for (int r = 0; r < 4; r++)
#pragma unroll
        for (int j = 0; j < 6; j++) {
            float s = pt[r][j];
            s += __shfl_xor_sync(0xffffffffu, s, 1);
            s += __shfl_xor_sync(0xffffffffu, s, 2);
            if ((lane & 3) == 0) {
                int row = mw * 32 + (r >> 1) * 16 + (lane >> 2) + (r & 1) * 8;
                red[(nw * 128 + row) * 6 + j] = s;
            }
        }
    __syncthreads();

    if (tid < 128) {
        int g = gsm[tid >> 5];
        if (g >= 0) {
            float o[6];
#pragma unroll
            for (int j = 0; j < 6; j++)
                o[j] = bn2[b * 6 + j] + red[tid * 6 + j] + red[(128 + tid) * 6 + j]
                     + red[(256 + tid) * 6 + j] + red[(384 + tid) * 6 + j];
            int node = g * 32 + (tid & 31);
            out[OFF_NHEAD + node * 3 + 0] = o[0];
            out[OFF_NHEAD + node * 3 + 1] = o[1];
            out[OFF_NHEAD + node * 3 + 2] = o[2];
            out[OFF_NVAR  + node * 3 + 0] = o[3] * o[3];
            out[OFF_NVAR  + node * 3 + 1] = o[4] * o[4];
            out[OFF_NVAR  + node * 3 + 2] = o[5] * o[5];
        }
    }
}

// ---------------------------------------------------------------------------
// graph branch: SIMT fp32, branch-sorted (132 CTAs x 32 graphs, one branch).
// ---------------------------------------------------------------------------
__global__ void __launch_bounds__(256) graph_k(
    const int* __restrict__ ds,
    const float* __restrict__ Wgs, const float* __restrict__ bgs,
    const float* __restrict__ Wgh, const float* __restrict__ bgh,
    float* __restrict__ out)
{
    extern __shared__ float smemf[];
    __shared__ int gidx[32];
    float* xs = smemf;                 // 32x256 = 32KB
    float* ws = smemf + 32 * 256;      // 16x256 = 16KB

    int tid = threadIdx.x;
    if (tid < 32) gidx[tid] = g_sched[blockIdx.x * 32 + tid];
    __syncthreads();

    int b = -1;
    for (int r = 0; r < 32; r++) {
        int g = gidx[r];
        if (g >= 0) { b = ds[g]; break; }
    }
    if (b < 0) return;

    for (int j = tid; j < 32 * 64; j += 256) {
        int row = j >> 6, q = j & 63;
        int g = gidx[row];
        if (g >= 0) ((float4*)xs)[j] = ((const float4*)g_xg)[g * 64 + q];
    }

    {
        const float* W = Wgs + (size_t)b * D * SH;
        const float* bias = bgs + b * SH;
        int r0 = (tid >> 5) * 4;
        int c0 = (tid & 31) * 4;
        float acc[4][8];
#pragma unroll
        for (int r = 0; r < 4; r++)
#pragma unroll
            for (int c = 0; c < 8; c++) acc[r][c] = 0.f;

        for (int kt = 0; kt < D; kt += 16) {
            __syncthreads();
            const float4* wsrc = (const float4*)(W + (size_t)kt * SH);
            float4* wdst = (float4*)ws;
#pragma unroll
            for (int j = tid; j < 16 * SH / 4; j += 256) wdst[j] = wsrc[j];
            __syncthreads();
#pragma unroll
            for (int dd = 0; dd < 16; dd++) {
                float xv0 = xs[(r0 + 0) * D + kt + dd];
                float xv1 = xs[(r0 + 1) * D + kt + dd];
                float xv2 = xs[(r0 + 2) * D + kt + dd];
                float xv3 = xs[(r0 + 3) * D + kt + dd];
                float4 wa = *(const float4*)&ws[dd * SH + c0];
                float4 wb = *(const float4*)&ws[dd * SH + c0 + 128];
                float wv[8] = {wa.x, wa.y, wa.z, wa.w, wb.x, wb.y, wb.z, wb.w};
#pragma unroll
                for (int c = 0; c < 8; c++) {
                    acc[0][c] += xv0 * wv[c];
                    acc[1][c] += xv1 * wv[c];
                    acc[2][c] += xv2 * wv[c];
                    acc[3][c] += xv3 * wv[c];
                }
            }
        }
        __syncthreads();
#pragma unroll
        for (int c = 0; c < 4; c++) {
            float b0 = bias[c0 + c];
            float b1 = bias[c0 + 128 + c];
#pragma unroll
            for (int r = 0; r < 4; r++) {
                xs[(r0 + r) * SH + c0 + c]       = fmaxf(acc[r][c]     + b0, 0.f);
                xs[(r0 + r) * SH + c0 + 128 + c] = fmaxf(acc[r][c + 4] + b1, 0.f);
            }
        }
        __syncthreads();
    }

    const float* W2 = Wgh + (size_t)b * SH * (2 * HDG);
    for (int j = tid; j < 32 * 2 * HDG; j += 256) {
        int i = j / (2 * HDG);
        int h = j % (2 * HDG);
        int g = gidx[i];
        if (g < 0) continue;
        float s = bgh[b * 2 * HDG + h];
#pragma unroll 8
        for (int k = 0; k < SH; k++) s += xs[i * SH + k] * W2[k * (2 * HDG) + h];
        if (h < HDG) out[OFF_GHEAD + g * HDG + h] = s;
        else         out[OFF_GVAR  + g * HDG + (h - HDG)] = s * s;
    }
}

// ---------------------------------------------------------------------------
extern "C" void kernel_launch(void* const* d_in, const int* in_sizes, int n_in,
                              void* d_out, int out_size)
{
    const float* x   = (const float*)d_in[0];
    const int*   ds  = (const int*)  d_in[1];
    const float* Wgs = (const float*)d_in[3];
    const float* bgs = (const float*)d_in[4];
    const float* Wgh = (const float*)d_in[5];
    const float* bgh = (const float*)d_in[6];
    const float* Wn1 = (const float*)d_in[7];
    const float* bn1 = (const float*)d_in[8];
    const float* Wn2 = (const float*)d_in[9];
    const float* bn2 = (const float*)d_in[10];
    float* out = (float*)d_out;

    cudaFuncSetAttribute(node_mma_k, cudaFuncAttributeMaxDynamicSharedMemorySize, SMTOT);
    cudaFuncSetAttribute(graph_k,    cudaFuncAttributeMaxDynamicSharedMemorySize, 49152);

    size_t smem_g = (32 * 256 + 16 * 256) * sizeof(float);   // 48KB dynamic

    prep_k<<<16, 256>>>(Wn1);
    sched_init_k<<<17, 256>>>();
    sched_fill_k<<<16, 256>>>(ds);
    node_mma_k<<<NCTA, 512, SMTOT>>>(x, ds, bn1, Wn2, bn2, out);
    graph_k<<<NSLOT / 32, 256, smem_g>>>(ds, Wgs, bgs, Wgh, bgh, out);
}